// round 5
// baseline (speedup 1.0000x reference)
#include <cuda_runtime.h>
#include <math.h>

// Problem constants
#define NC    22            // columns
#define NE    12            // embeddings per column
#define DD    64            // feature dim
#define BB    2048          // batch
#define NPAIR 231           // 22 choose 2
#define NENT  253           // 22 lin/diag entries + 231 pair entries
#define TBL   (NC*NE)       // 264 table rows per d-slice
#define NBT   4             // b-tiles
#define BT    (BB/NBT)      // 512 b per tile

typedef unsigned long long ull;

// ---------------- device scratch ----------------
__device__ float g_partial[BB * 2 * DD];    // partial[(b*2+k)][d]
__device__ unsigned g_cnt[NBT];             // arrival counters (never reset; modulo)

// ---------------- f32x2 packed helpers (sm_100a+) ----------------
__device__ __forceinline__ ull pack2(float lo, float hi) {
    ull r; asm("mov.b64 %0, {%1, %2};" : "=l"(r) : "f"(lo), "f"(hi)); return r;
}
__device__ __forceinline__ void unpack2(ull x, float& lo, float& hi) {
    asm("mov.b64 {%0, %1}, %2;" : "=f"(lo), "=f"(hi) : "l"(x));
}
__device__ __forceinline__ ull fma2(ull a, ull b, ull c) {
    ull r; asm("fma.rn.f32x2 %0, %1, %2, %3;" : "=l"(r) : "l"(a), "l"(b), "l"(c)); return r;
}
__device__ __forceinline__ ull mul2(ull a, ull b) {
    ull r; asm("mul.rn.f32x2 %0, %1, %2;" : "=l"(r) : "l"(a), "l"(b)); return r;
}

// ---------------- single fused kernel -------------------------------------------
// grid: (NBT, DD) = (4, 64), 256 threads. Each block: one d, 512 b (2 per thread
// packed f32x2). Prologue recomputes this d's combined weights + tables from the
// raw inputs. Epilogue: last-arriving block per btile reduces partials over d.
__global__ void __launch_bounds__(256)
fused_kernel(const int* __restrict__ idx, const float* __restrict__ emb_mean,
             const float* __restrict__ emb_std, const float* __restrict__ v,
             const float* __restrict__ W_ops, const float* __restrict__ W_cat,
             const float* __restrict__ log_alpha, float* __restrict__ out) {
    const int btile = blockIdx.x;
    const int d  = blockIdx.y;
    const int tid = threadIdx.x;

    __shared__ float  swt[NENT * 8];     // duplicated weights
    __shared__ float  mean_s[TBL];       // per-d embedding-mean slice
    __shared__ float  sp_s[TBL];         // per-d softplus slice
    __shared__ float2 sc[NC * NC];       // per-ordered-pair linear contribution
    __shared__ unsigned isLastS;

    // ---- softmax(log_alpha), every thread (trivial) ----
    float w0, w1, w2, w3, w4;
    {
        float la[5], w[5];
        float mx = -1e30f, s = 0.f;
        #pragma unroll
        for (int z = 0; z < 5; z++) { la[z] = __ldg(log_alpha + z); mx = fmaxf(mx, la[z]); }
        #pragma unroll
        for (int z = 0; z < 5; z++) { w[z] = expf(la[z] - mx); s += w[z]; }
        float inv = 1.0f / s;
        w0 = w[0]*inv; w1 = w[1]*inv; w2 = w[2]*inv; w3 = w[3]*inv; w4 = w[4]*inv;
    }

    // ---- phase 1: tables + per-ordered-pair weight contributions ----
    const float2* W2 = reinterpret_cast<const float2*>(W_ops);
    const float2* C2 = reinterpret_cast<const float2*>(W_cat);

    for (int t = tid; t < TBL; t += 256) {
        mean_s[t] = emb_mean[t * DD + d];
        float x = emb_std[t * DD + d];
        sp_s[t] = 0.01f * (fmaxf(x, 0.0f) + log1pf(expf(-fabsf(x))));
    }

    for (int ij = tid; ij < NC * NC; ij += 256) {
        int i = ij / NC;
        int j = ij - i * NC;
        float2 Pij = W2[((i*NC+j)*4 + 0)*DD + d];
        float2 Pji = W2[((j*NC+i)*4 + 0)*DD + d];
        float2 Mij = W2[((i*NC+j)*4 + 1)*DD + d];
        float2 Mji = W2[((j*NC+i)*4 + 1)*DD + d];
        float2 Xij = W2[((i*NC+j)*4 + 2)*DD + d];
        float2 Xji = W2[((j*NC+i)*4 + 2)*DD + d];
        float2 Nij = W2[((i*NC+j)*4 + 3)*DD + d];
        float2 Nji = W2[((j*NC+i)*4 + 3)*DD + d];
        float2 Cp  = C2[(i*NC+j)*(2*DD) + d];        // p half, row d
        float2 Cq  = C2[(j*NC+i)*(2*DD) + DD + d];   // q half, row 64+d

        float c0 = w0*(Pij.x+Pji.x) + 0.5f*w2*(Xij.x+Xji.x)
                 + 0.5f*w3*(Nij.x+Nji.x) + w4*(Cp.x+Cq.x);
        float c1 = w0*(Pij.y+Pji.y) + 0.5f*w2*(Xij.y+Xji.y)
                 + 0.5f*w3*(Nij.y+Nji.y) + w4*(Cp.y+Cq.y);
        sc[ij] = make_float2(c0, c1);

        if (i == j) {
            reinterpret_cast<float4*>(swt)[i * 2 + 1] =
                make_float4(w1*Mij.x, w1*Mij.x, w1*Mij.y, w1*Mij.y);
        } else if (i < j) {
            float wx = w1*(Mij.x+Mji.x);
            float wy = w1*(Mij.y+Mji.y);
            float wz = 0.5f*(w2*(Xij.x+Xji.x) - w3*(Nij.x+Nji.x));
            float ww = 0.5f*(w2*(Xij.y+Xji.y) - w3*(Nij.y+Nji.y));
            int entry = NC + (i*(2*NC - 1 - i))/2 + (j - i - 1);
            float4* dst = reinterpret_cast<float4*>(swt) + entry * 2;
            dst[0] = make_float4(wx, wx, wy, wy);
            dst[1] = make_float4(wz, wz, ww, ww);
        }
    }
    __syncthreads();

    // ---- phase 2: linear weights (reduce sc over j) ----
    if (tid < NC) {
        float l0 = 0.f, l1 = 0.f;
        #pragma unroll
        for (int j = 0; j < NC; j++) {
            float2 c = sc[tid * NC + j];
            l0 += c.x; l1 += c.y;
        }
        reinterpret_cast<float4*>(swt)[tid * 2] = make_float4(l0, l0, l1, l1);
    }
    __syncthreads();

    // ---- main pairwise phase ----
    const int b  = btile * BT + tid;
    const int b2 = b + 256;
    const float vlo = v[b  * DD + d];
    const float vhi = v[b2 * DD + d];

    ull e2[NC];
    #pragma unroll
    for (int i = 0; i < NC; i++) {
        int iv  = idx[i * BB + b];
        int iv2 = idx[i * BB + b2];
        float elo = fmaf(sp_s[i * NE + iv],  vlo, mean_s[i * NE + iv]);
        float ehi = fmaf(sp_s[i * NE + iv2], vhi, mean_s[i * NE + iv2]);
        e2[i] = pack2(elo, ehi);
    }

    ull A0 = 0ULL, A1 = 0ULL;
    const ulonglong2* sw2 = reinterpret_cast<const ulonglong2*>(swt);

    #pragma unroll
    for (int i = 0; i < NC; i++) {
        ulonglong2 wl = sw2[i * 2 + 0];
        ulonglong2 wd = sw2[i * 2 + 1];
        ull p2 = mul2(e2[i], e2[i]);
        A0 = fma2(e2[i], wl.x, A0);
        A1 = fma2(e2[i], wl.y, A1);
        A0 = fma2(p2,    wd.x, A0);
        A1 = fma2(p2,    wd.y, A1);
    }

    const ull NEG1 = 0xBF800000BF800000ULL;
    int pi = NC;
    #pragma unroll
    for (int i = 0; i < NC - 1; i++) {
        #pragma unroll
        for (int j = i + 1; j < NC; j++) {
            ulonglong2 wm = sw2[pi * 2 + 0];
            ulonglong2 wa = sw2[pi * 2 + 1];
            pi++;
            ull p2 = mul2(e2[i], e2[j]);
            ull df = fma2(e2[j], NEG1, e2[i]);
            ull ad = df & 0x7FFFFFFF7FFFFFFFULL;
            A0 = fma2(p2, wm.x, A0);
            A1 = fma2(p2, wm.y, A1);
            A0 = fma2(ad, wa.x, A0);
            A1 = fma2(ad, wa.y, A1);
        }
    }

    float a0l, a0h, a1l, a1h;
    unpack2(A0, a0l, a0h);
    unpack2(A1, a1l, a1h);
    // layout: partial[(b*2+k)][d] (contiguous per btile for the reducer)
    g_partial[(b  * 2 + 0) * DD + d] = a0l;
    g_partial[(b  * 2 + 1) * DD + d] = a1l;
    g_partial[(b2 * 2 + 0) * DD + d] = a0h;
    g_partial[(b2 * 2 + 1) * DD + d] = a1h;

    // ---- last-block-per-btile reduction over d ----
    __threadfence();       // publish this thread's partial stores device-wide
    __syncthreads();       // all threads' fences precede tid0's arrival
    if (tid == 0) {
        unsigned old = atomicAdd(&g_cnt[btile], 1u);
        isLastS = ((old % DD) == (DD - 1)) ? 1u : 0u;
    }
    __syncthreads();
    if (isLastS) {
        __threadfence();   // acquire side: see all other blocks' partials
        // outputs o in [btile*1024, btile*1024 + 1024); out[o] = sum_d P[o*64+d]
        const int obase = btile * (BT * 2);
        for (int o = tid; o < BT * 2; o += 256) {
            const float4* p = reinterpret_cast<const float4*>(g_partial + (obase + o) * DD);
            float s = 0.f;
            #pragma unroll
            for (int q = 0; q < DD / 4; q++) {
                float4 x = p[q];
                s += (x.x + x.y) + (x.z + x.w);
            }
            out[obase + o] = s;
        }
    }
}

// ---------------- launch ----------------------------------------------------------
extern "C" void kernel_launch(void* const* d_in, const int* in_sizes, int n_in,
                              void* d_out, int out_size) {
    const int*   idx       = (const int*)  d_in[0];
    const float* emb_mean  = (const float*)d_in[1];
    const float* emb_std   = (const float*)d_in[2];
    const float* v         = (const float*)d_in[3];
    const float* W_ops     = (const float*)d_in[4];
    const float* W_cat     = (const float*)d_in[5];
    const float* log_alpha = (const float*)d_in[6];
    float* out = (float*)d_out;

    fused_kernel<<<dim3(NBT, DD), 256>>>(idx, emb_mean, emb_std, v,
                                         W_ops, W_cat, log_alpha, out);
}

// round 6
// speedup vs baseline: 1.0741x; 1.0741x over previous
#include <cuda_runtime.h>
#include <math.h>

// Problem constants
#define NC    22            // columns
#define NE    12            // embeddings per column
#define DD    64            // feature dim
#define BB    2048          // batch
#define NPAIR 231           // 22 choose 2
#define NENT  253           // 22 lin/diag entries + 231 pair entries
#define TBL   (NC*NE)       // 264 table rows
#define NBT   4             // b-tiles
#define BT    (BB/NBT)      // 512 b per tile
#define NBLK  (NBT*DD)      // 256 blocks total

typedef unsigned long long ull;

// ---------------- device scratch ----------------
__device__ float  g_sp[TBL * DD];           // 0.01*softplus(emb_std), [t][d] flat
__device__ float  g_w[DD * NENT * 8];       // per-d lane-duplicated packed weights
__device__ float2 g_c[NC * NC * DD];        // linear contribution of ordered (i,j) at d
__device__ float  g_partial[BB * 2 * DD];   // partial[(b*2+k)][d]
__device__ unsigned g_bar;                  // global barrier counter (monotonic)
__device__ unsigned g_cnt[NBT];             // btile arrival counters (monotonic)

// ---------------- f32x2 packed helpers (sm_100a+) ----------------
__device__ __forceinline__ ull pack2(float lo, float hi) {
    ull r; asm("mov.b64 %0, {%1, %2};" : "=l"(r) : "f"(lo), "f"(hi)); return r;
}
__device__ __forceinline__ void unpack2(ull x, float& lo, float& hi) {
    asm("mov.b64 {%0, %1}, %2;" : "=f"(lo), "=f"(hi) : "l"(x));
}
__device__ __forceinline__ ull fma2(ull a, ull b, ull c) {
    ull r; asm("fma.rn.f32x2 %0, %1, %2, %3;" : "=l"(r) : "l"(a), "l"(b), "l"(c)); return r;
}
__device__ __forceinline__ ull mul2(ull a, ull b) {
    ull r; asm("mul.rn.f32x2 %0, %1, %2;" : "=l"(r) : "l"(a), "l"(b)); return r;
}

// ---------------- single fused kernel with software grid barrier -----------------
__global__ void __launch_bounds__(256, 2)
fused_kernel(const int* __restrict__ idx, const float* __restrict__ emb_mean,
             const float* __restrict__ emb_std, const float* __restrict__ v,
             const float* __restrict__ W_ops, const float* __restrict__ W_cat,
             const float* __restrict__ log_alpha, float* __restrict__ out) {
    const int btile = blockIdx.x;          // 0..3
    const int d     = blockIdx.y;          // 0..63
    const int tid   = threadIdx.x;         // 0..255
    const int gid   = (d * NBT + btile) * 256 + tid;   // 0..65535

    __shared__ float    swt[NENT * 8];
    __shared__ float    mean_s[TBL];
    __shared__ float    sp_s[TBL];
    __shared__ unsigned flagS;

    // ================= PHASE 1: distributed prep (each item done once) =========
    {
        // softmax over 5 primitives (every thread; trivial)
        float la[5], w[5];
        float mx = -1e30f, s = 0.f;
        #pragma unroll
        for (int z = 0; z < 5; z++) { la[z] = __ldg(log_alpha + z); mx = fmaxf(mx, la[z]); }
        #pragma unroll
        for (int z = 0; z < 5; z++) { w[z] = expf(la[z] - mx); s += w[z]; }
        float inv = 1.0f / s;
        const float w0 = w[0]*inv, w1 = w[1]*inv, w2 = w[2]*inv,
                    w3 = w[3]*inv, w4 = w[4]*inv;

        if (gid < NC * NC * DD) {                       // 30976 weight items
            int pd = gid & 63;
            int ij = gid >> 6;
            int i = ij / NC;
            int j = ij - i * NC;

            const float2* W2 = reinterpret_cast<const float2*>(W_ops);
            const float2* C2 = reinterpret_cast<const float2*>(W_cat);

            float2 Pij = W2[((i*NC+j)*4 + 0)*DD + pd];
            float2 Pji = W2[((j*NC+i)*4 + 0)*DD + pd];
            float2 Mij = W2[((i*NC+j)*4 + 1)*DD + pd];
            float2 Xij = W2[((i*NC+j)*4 + 2)*DD + pd];
            float2 Xji = W2[((j*NC+i)*4 + 2)*DD + pd];
            float2 Nij = W2[((i*NC+j)*4 + 3)*DD + pd];
            float2 Nji = W2[((j*NC+i)*4 + 3)*DD + pd];
            float2 Cp  = C2[(i*NC+j)*(2*DD) + pd];        // p half, row d
            float2 Cq  = C2[(j*NC+i)*(2*DD) + DD + pd];   // q half, row 64+d

            float c0 = w0*(Pij.x+Pji.x) + 0.5f*w2*(Xij.x+Xji.x)
                     + 0.5f*w3*(Nij.x+Nji.x) + w4*(Cp.x+Cq.x);
            float c1 = w0*(Pij.y+Pji.y) + 0.5f*w2*(Xij.y+Xji.y)
                     + 0.5f*w3*(Nij.y+Nji.y) + w4*(Cp.y+Cq.y);
            g_c[ij * DD + pd] = make_float2(c0, c1);

            if (i == j) {
                reinterpret_cast<float4*>(g_w)[(pd*NENT + i) * 2 + 1] =
                    make_float4(w1*Mij.x, w1*Mij.x, w1*Mij.y, w1*Mij.y);
            } else if (i < j) {
                float2 Mji = W2[((j*NC+i)*4 + 1)*DD + pd];
                float wx = w1*(Mij.x+Mji.x);
                float wy = w1*(Mij.y+Mji.y);
                float wz = 0.5f*(w2*(Xij.x+Xji.x) - w3*(Nij.x+Nji.x));
                float ww = 0.5f*(w2*(Xij.y+Xji.y) - w3*(Nij.y+Nji.y));
                int entry = NC + (i*(2*NC - 1 - i))/2 + (j - i - 1);
                float4* dst = reinterpret_cast<float4*>(g_w) + (pd*NENT + entry) * 2;
                dst[0] = make_float4(wx, wx, wy, wy);
                dst[1] = make_float4(wz, wz, ww, ww);
            }
        } else if (gid < NC * NC * DD + TBL * DD) {     // 16896 softplus items
            int u = gid - NC * NC * DD;
            float x = emb_std[u];
            g_sp[u] = 0.01f * (fmaxf(x, 0.0f) + log1pf(expf(-fabsf(x))));
        }
    }

    // ================= GRID-WIDE BARRIER ========================================
    __threadfence();                // release: publish phase-1 stores
    __syncthreads();
    if (tid == 0) {
        unsigned old = atomicAdd(&g_bar, 1u);
        unsigned target = (old / NBLK + 1u) * NBLK;
        volatile unsigned* barp = &g_bar;
        while (*barp < target) { }
        flagS = 1u;
    }
    __syncthreads();
    __threadfence();                // acquire: see all blocks' phase-1 stores
    (void)flagS;

    // ================= PHASE 2a: per-block prologue (smem staging) ==============
    {
        const float4* wp = reinterpret_cast<const float4*>(g_w) + d * NENT * 2;
        float4* s4 = reinterpret_cast<float4*>(swt);
        #pragma unroll
        for (int t = tid; t < NENT * 2; t += 256) s4[t] = wp[t];
        for (int t = tid; t < TBL; t += 256) {
            mean_s[t] = emb_mean[t * DD + d];
            sp_s[t]   = g_sp[t * DD + d];
        }
        if (tid < NC) {             // linear weights: reduce g_c over j for this d
            float l0 = 0.f, l1 = 0.f;
            #pragma unroll
            for (int j = 0; j < NC; j++) {
                float2 c = g_c[(tid*NC + j)*DD + d];
                l0 += c.x; l1 += c.y;
            }
            reinterpret_cast<float4*>(swt)[tid * 2] = make_float4(l0, l0, l1, l1);
        }
    }
    __syncthreads();

    // ================= PHASE 2b: main pairwise compute ==========================
    const int b  = btile * BT + tid;
    const int b2 = b + 256;
    const float vlo = v[b  * DD + d];
    const float vhi = v[b2 * DD + d];

    ull e2[NC];
    #pragma unroll
    for (int i = 0; i < NC; i++) {
        int iv  = idx[i * BB + b];
        int iv2 = idx[i * BB + b2];
        float elo = fmaf(sp_s[i * NE + iv],  vlo, mean_s[i * NE + iv]);
        float ehi = fmaf(sp_s[i * NE + iv2], vhi, mean_s[i * NE + iv2]);
        e2[i] = pack2(elo, ehi);
    }

    ull A0 = 0ULL, A1 = 0ULL;
    const ulonglong2* sw2 = reinterpret_cast<const ulonglong2*>(swt);

    #pragma unroll
    for (int i = 0; i < NC; i++) {
        ulonglong2 wl = sw2[i * 2 + 0];
        ulonglong2 wd = sw2[i * 2 + 1];
        ull p2 = mul2(e2[i], e2[i]);
        A0 = fma2(e2[i], wl.x, A0);
        A1 = fma2(e2[i], wl.y, A1);
        A0 = fma2(p2,    wd.x, A0);
        A1 = fma2(p2,    wd.y, A1);
    }

    const ull NEG1 = 0xBF800000BF800000ULL;
    int pi = NC;
    #pragma unroll
    for (int i = 0; i < NC - 1; i++) {
        #pragma unroll
        for (int j = i + 1; j < NC; j++) {
            ulonglong2 wm = sw2[pi * 2 + 0];
            ulonglong2 wa = sw2[pi * 2 + 1];
            pi++;
            ull p2 = mul2(e2[i], e2[j]);
            ull df = fma2(e2[j], NEG1, e2[i]);
            ull ad = df & 0x7FFFFFFF7FFFFFFFULL;
            A0 = fma2(p2, wm.x, A0);
            A1 = fma2(p2, wm.y, A1);
            A0 = fma2(ad, wa.x, A0);
            A1 = fma2(ad, wa.y, A1);
        }
    }

    float a0l, a0h, a1l, a1h;
    unpack2(A0, a0l, a0h);
    unpack2(A1, a1l, a1h);
    g_partial[(b  * 2 + 0) * DD + d] = a0l;
    g_partial[(b  * 2 + 1) * DD + d] = a1l;
    g_partial[(b2 * 2 + 0) * DD + d] = a0h;
    g_partial[(b2 * 2 + 1) * DD + d] = a1h;

    // ================= PHASE 3: last-block-per-btile reduce over d ==============
    __threadfence();
    __syncthreads();
    if (tid == 0) {
        unsigned old = atomicAdd(&g_cnt[btile], 1u);
        flagS = ((old % DD) == (DD - 1)) ? 1u : 0u;
    }
    __syncthreads();
    if (flagS) {
        __threadfence();
        const int obase = btile * (BT * 2);
        for (int o = tid; o < BT * 2; o += 256) {
            const float4* p = reinterpret_cast<const float4*>(g_partial + (obase + o) * DD);
            float s = 0.f;
            #pragma unroll
            for (int q = 0; q < DD / 4; q++) {
                float4 x = p[q];
                s += (x.x + x.y) + (x.z + x.w);
            }
            out[obase + o] = s;
        }
    }
}

// ---------------- launch ----------------------------------------------------------
extern "C" void kernel_launch(void* const* d_in, const int* in_sizes, int n_in,
                              void* d_out, int out_size) {
    const int*   idx       = (const int*)  d_in[0];
    const float* emb_mean  = (const float*)d_in[1];
    const float* emb_std   = (const float*)d_in[2];
    const float* v         = (const float*)d_in[3];
    const float* W_ops     = (const float*)d_in[4];
    const float* W_cat     = (const float*)d_in[5];
    const float* log_alpha = (const float*)d_in[6];
    float* out = (float*)d_out;

    fused_kernel<<<dim3(NBT, DD), 256>>>(idx, emb_mean, emb_std, v,
                                         W_ops, W_cat, log_alpha, out);
}

// round 7
// speedup vs baseline: 1.1491x; 1.0699x over previous
#include <cuda_runtime.h>
#include <math.h>

// Problem constants
#define NC    22            // columns
#define NE    12            // embeddings per column
#define DD    64            // feature dim
#define BB    2048          // batch
#define NPAIR 231           // 22 choose 2
#define NENT  253           // 22 lin/diag entries + 231 pair entries
#define TBL   (NC*NE)       // 264 table rows
#define NBT   16            // b-tiles (main grid.x)
#define BT    (BB/NBT)      // 128 b per tile

typedef unsigned long long ull;

// ---------------- device scratch ----------------
__device__ float  g_sp[TBL * DD];           // 0.01*softplus(emb_std), flat [t*DD+d]
__device__ float  g_w[DD * NENT * 8];       // per-d lane-duplicated packed weights
__device__ float2 g_c[NC * NC * DD];        // linear contribution of ordered (i,j) at d
__device__ float  g_partial[BB * 2 * DD];   // partial[(b*2+k)][d]
__device__ unsigned g_cnt[NBT];             // btile arrival counters (monotonic)

// ---------------- f32x2 packed helpers (sm_100a+) ----------------
__device__ __forceinline__ ull pack2(float lo, float hi) {
    ull r; asm("mov.b64 %0, {%1, %2};" : "=l"(r) : "f"(lo), "f"(hi)); return r;
}
__device__ __forceinline__ void unpack2(ull x, float& lo, float& hi) {
    asm("mov.b64 {%0, %1}, %2;" : "=f"(lo), "=f"(hi) : "l"(x));
}
__device__ __forceinline__ ull fma2(ull a, ull b, ull c) {
    ull r; asm("fma.rn.f32x2 %0, %1, %2, %3;" : "=l"(r) : "l"(a), "l"(b), "l"(c)); return r;
}
__device__ __forceinline__ ull mul2(ull a, ull b) {
    ull r; asm("mul.rn.f32x2 %0, %1, %2;" : "=l"(r) : "l"(a), "l"(b)); return r;
}

// ---------------- prep kernel (64-thread blocks for SM spread) --------------------
// blocks [0, 484): one thread per (i,j,d) weight item (484*64 = 30976 exactly)
// blocks [484, 748): softplus items (264*64 = 16896 exactly)
#define WBLK 484
#define PBLK (WBLK + TBL)    // 748

__global__ void __launch_bounds__(64)
prep_kernel(const float* __restrict__ W_ops, const float* __restrict__ W_cat,
            const float* __restrict__ log_alpha, const float* __restrict__ emb_std) {
    if (blockIdx.x >= WBLK) {
        int u = (blockIdx.x - WBLK) * 64 + threadIdx.x;   // < TBL*DD
        float x = emb_std[u];
        g_sp[u] = 0.01f * (fmaxf(x, 0.0f) + log1pf(expf(-fabsf(x))));
        return;
    }
    int t = blockIdx.x * 64 + threadIdx.x;
    int d  = t & 63;
    int ij = t >> 6;
    int i = ij / NC;
    int j = ij - i * NC;

    // softmax over 5 primitives (trivial per-thread)
    float la[5], w[5];
    float mx = -1e30f, s = 0.f;
    #pragma unroll
    for (int z = 0; z < 5; z++) { la[z] = __ldg(log_alpha + z); mx = fmaxf(mx, la[z]); }
    #pragma unroll
    for (int z = 0; z < 5; z++) { w[z] = expf(la[z] - mx); s += w[z]; }
    float inv = 1.0f / s;
    const float w0 = w[0]*inv, w1 = w[1]*inv, w2 = w[2]*inv,
                w3 = w[3]*inv, w4 = w[4]*inv;

    const float2* W2 = reinterpret_cast<const float2*>(W_ops);
    const float2* C2 = reinterpret_cast<const float2*>(W_cat);

    float2 Pij = W2[((i*NC+j)*4 + 0)*DD + d];
    float2 Pji = W2[((j*NC+i)*4 + 0)*DD + d];
    float2 Mij = W2[((i*NC+j)*4 + 1)*DD + d];
    float2 Xij = W2[((i*NC+j)*4 + 2)*DD + d];
    float2 Xji = W2[((j*NC+i)*4 + 2)*DD + d];
    float2 Nij = W2[((i*NC+j)*4 + 3)*DD + d];
    float2 Nji = W2[((j*NC+i)*4 + 3)*DD + d];
    float2 Cp  = C2[(i*NC+j)*(2*DD) + d];        // p half, row d
    float2 Cq  = C2[(j*NC+i)*(2*DD) + DD + d];   // q half, row 64+d

    float c0 = w0*(Pij.x+Pji.x) + 0.5f*w2*(Xij.x+Xji.x)
             + 0.5f*w3*(Nij.x+Nji.x) + w4*(Cp.x+Cq.x);
    float c1 = w0*(Pij.y+Pji.y) + 0.5f*w2*(Xij.y+Xji.y)
             + 0.5f*w3*(Nij.y+Nji.y) + w4*(Cp.y+Cq.y);
    g_c[ij * DD + d] = make_float2(c0, c1);

    if (i == j) {
        reinterpret_cast<float4*>(g_w)[(d*NENT + i) * 2 + 1] =
            make_float4(w1*Mij.x, w1*Mij.x, w1*Mij.y, w1*Mij.y);
    } else if (i < j) {
        float2 Mji = W2[((j*NC+i)*4 + 1)*DD + d];
        float wx = w1*(Mij.x+Mji.x);
        float wy = w1*(Mij.y+Mji.y);
        float wz = 0.5f*(w2*(Xij.x+Xji.x) - w3*(Nij.x+Nji.x));
        float ww = 0.5f*(w2*(Xij.y+Xji.y) - w3*(Nij.y+Nji.y));
        int entry = NC + (i*(2*NC - 1 - i))/2 + (j - i - 1);
        float4* dst = reinterpret_cast<float4*>(g_w) + (d*NENT + entry) * 2;
        dst[0] = make_float4(wx, wx, wy, wy);
        dst[1] = make_float4(wz, wz, ww, ww);
    }
}

// ---------------- main kernel: pairwise compute + fused d-reduce tail -------------
// grid: (NBT, DD) = (16, 64), 64 threads; 2 b per thread packed f32x2.
__global__ void __launch_bounds__(64)
main_kernel(const int* __restrict__ idx, const float* __restrict__ emb_mean,
            const float* __restrict__ v, float* __restrict__ out) {
    const int d  = blockIdx.y;
    const int btile = blockIdx.x;
    const int b0 = btile * BT;
    const int tid = threadIdx.x;

    __shared__ float swt[NENT * 8];
    __shared__ float mean_s[TBL];
    __shared__ float sp_s[TBL];
    __shared__ unsigned isLastS;

    {
        const float4* wp = reinterpret_cast<const float4*>(g_w) + d * NENT * 2;
        float4* s4 = reinterpret_cast<float4*>(swt);
        #pragma unroll 4
        for (int t = tid; t < NENT * 2; t += 64) s4[t] = wp[t];
        for (int t = tid; t < TBL; t += 64) {
            mean_s[t] = emb_mean[t * DD + d];
            sp_s[t]   = g_sp[t * DD + d];
        }
        if (tid < NC) {             // linear weights: reduce g_c over j for this d
            float l0 = 0.f, l1 = 0.f;
            #pragma unroll
            for (int j = 0; j < NC; j++) {
                float2 c = g_c[(tid*NC + j)*DD + d];
                l0 += c.x; l1 += c.y;
            }
            reinterpret_cast<float4*>(swt)[tid * 2] = make_float4(l0, l0, l1, l1);
        }
    }
    __syncthreads();

    const int b  = b0 + tid;
    const int b2 = b + 64;
    const float vlo = v[b  * DD + d];
    const float vhi = v[b2 * DD + d];

    ull e2[NC];
    #pragma unroll
    for (int i = 0; i < NC; i++) {
        int iv  = idx[i * BB + b];
        int iv2 = idx[i * BB + b2];
        float elo = fmaf(sp_s[i * NE + iv],  vlo, mean_s[i * NE + iv]);
        float ehi = fmaf(sp_s[i * NE + iv2], vhi, mean_s[i * NE + iv2]);
        e2[i] = pack2(elo, ehi);
    }

    ull A0 = 0ULL, A1 = 0ULL;
    const ulonglong2* sw2 = reinterpret_cast<const ulonglong2*>(swt);

    #pragma unroll
    for (int i = 0; i < NC; i++) {
        ulonglong2 wl = sw2[i * 2 + 0];
        ulonglong2 wd = sw2[i * 2 + 1];
        ull p2 = mul2(e2[i], e2[i]);
        A0 = fma2(e2[i], wl.x, A0);
        A1 = fma2(e2[i], wl.y, A1);
        A0 = fma2(p2,    wd.x, A0);
        A1 = fma2(p2,    wd.y, A1);
    }

    const ull NEG1 = 0xBF800000BF800000ULL;
    int pi = NC;
    #pragma unroll
    for (int i = 0; i < NC - 1; i++) {
        #pragma unroll
        for (int j = i + 1; j < NC; j++) {
            ulonglong2 wm = sw2[pi * 2 + 0];
            ulonglong2 wa = sw2[pi * 2 + 1];
            pi++;
            ull p2 = mul2(e2[i], e2[j]);
            ull df = fma2(e2[j], NEG1, e2[i]);
            ull ad = df & 0x7FFFFFFF7FFFFFFFULL;
            A0 = fma2(p2, wm.x, A0);
            A1 = fma2(p2, wm.y, A1);
            A0 = fma2(ad, wa.x, A0);
            A1 = fma2(ad, wa.y, A1);
        }
    }

    float a0l, a0h, a1l, a1h;
    unpack2(A0, a0l, a0h);
    unpack2(A1, a1l, a1h);
    // layout: partial[(b*2+k)][d] (contiguous slab per btile for the reducer)
    g_partial[(b  * 2 + 0) * DD + d] = a0l;
    g_partial[(b  * 2 + 1) * DD + d] = a1l;
    g_partial[(b2 * 2 + 0) * DD + d] = a0h;
    g_partial[(b2 * 2 + 1) * DD + d] = a1h;

    // ---- last-block-per-btile reduction over d (threadFenceReduction pattern) ----
    __threadfence();       // publish partial stores device-wide
    __syncthreads();       // all threads' stores precede tid0's arrival
    if (tid == 0) {
        unsigned old = atomicAdd(&g_cnt[btile], 1u);
        isLastS = ((old % DD) == (DD - 1)) ? 1u : 0u;   // monotonic: replay-safe
    }
    __syncthreads();
    if (isLastS) {
        __threadfence();   // acquire: see all 64 d-blocks' partials
        const int obase = btile * (BT * 2);
        for (int o = tid; o < BT * 2; o += 64) {        // 4 outputs per thread
            const float4* p = reinterpret_cast<const float4*>(g_partial + (obase + o) * DD);
            float s = 0.f;
            #pragma unroll
            for (int q = 0; q < DD / 4; q++) {
                float4 x = p[q];
                s += (x.x + x.y) + (x.z + x.w);
            }
            out[obase + o] = s;
        }
    }
}

// ---------------- launch ----------------------------------------------------------
extern "C" void kernel_launch(void* const* d_in, const int* in_sizes, int n_in,
                              void* d_out, int out_size) {
    const int*   idx       = (const int*)  d_in[0];
    const float* emb_mean  = (const float*)d_in[1];
    const float* emb_std   = (const float*)d_in[2];
    const float* v         = (const float*)d_in[3];
    const float* W_ops     = (const float*)d_in[4];
    const float* W_cat     = (const float*)d_in[5];
    const float* log_alpha = (const float*)d_in[6];
    float* out = (float*)d_out;

    prep_kernel<<<PBLK, 64>>>(W_ops, W_cat, log_alpha, emb_std);
    main_kernel<<<dim3(NBT, DD), 64>>>(idx, emb_mean, v, out);
}

// round 8
// speedup vs baseline: 1.1952x; 1.0401x over previous
#include <cuda_runtime.h>
#include <math.h>

// Problem constants
#define NC    22            // columns
#define NE    12            // embeddings per column
#define DD    64            // feature dim
#define BB    2048          // batch
#define NPAIR 231           // 22 choose 2
#define NENT  253           // 22 lin/diag entries + 231 pair entries
#define TBL   (NC*NE)       // 264 table rows

typedef unsigned long long ull;

// ---------------- device scratch ----------------
__device__ float g_sp[TBL * DD];            // 0.01*softplus(emb_std), flat [t*DD+d]
__device__ float g_w[DD * NENT * 8];        // per-d lane-duplicated packed weights
__device__ float g_partial[BB * 2 * DD];    // partial[(b*2+k)][d]

// ---------------- f32x2 packed helpers (sm_100a+) ----------------
__device__ __forceinline__ ull pack2(float lo, float hi) {
    ull r; asm("mov.b64 %0, {%1, %2};" : "=l"(r) : "f"(lo), "f"(hi)); return r;
}
__device__ __forceinline__ void unpack2(ull x, float& lo, float& hi) {
    asm("mov.b64 {%0, %1}, %2;" : "=f"(lo), "=f"(hi) : "l"(x));
}
__device__ __forceinline__ ull fma2(ull a, ull b, ull c) {
    ull r; asm("fma.rn.f32x2 %0, %1, %2, %3;" : "=l"(r) : "l"(a), "l"(b), "l"(c)); return r;
}
__device__ __forceinline__ ull mul2(ull a, ull b) {
    ull r; asm("mul.rn.f32x2 %0, %1, %2;" : "=l"(r) : "l"(a), "l"(b)); return r;
}

__device__ __forceinline__ void softmax5(const float* __restrict__ log_alpha,
                                         float& w0, float& w1, float& w2,
                                         float& w3, float& w4) {
    float la[5], w[5];
    float mx = -1e30f, s = 0.f;
    #pragma unroll
    for (int z = 0; z < 5; z++) { la[z] = __ldg(log_alpha + z); mx = fmaxf(mx, la[z]); }
    #pragma unroll
    for (int z = 0; z < 5; z++) { w[z] = expf(la[z] - mx); s += w[z]; }
    float inv = 1.0f / s;
    w0 = w[0]*inv; w1 = w[1]*inv; w2 = w[2]*inv; w3 = w[3]*inv; w4 = w[4]*inv;
}

// ---------------- prep kernel --------------------------------------------------
// blocks [0, 253): one packed-weight entry per block (threadIdx = d)
// blocks [253, 517): softplus table (264 blocks x 64 items)
// blocks [517, 539): linear weights, block = i (threadIdx = d)
#define EBLK 253
#define SBLK TBL                 // 264
#define LBLK NC                  // 22
#define PBLK (EBLK + SBLK + LBLK)

__global__ void __launch_bounds__(64)
prep_kernel(const float* __restrict__ W_ops, const float* __restrict__ W_cat,
            const float* __restrict__ log_alpha, const float* __restrict__ emb_std) {
    const int blk = blockIdx.x;
    const int d = threadIdx.x;

    if (blk >= EBLK && blk < EBLK + SBLK) {          // softplus
        int u = (blk - EBLK) * 64 + d;
        float x = emb_std[u];
        g_sp[u] = 0.01f * (fmaxf(x, 0.0f) + log1pf(expf(-fabsf(x))));
        return;
    }

    float w0, w1, w2, w3, w4;
    softmax5(log_alpha, w0, w1, w2, w3, w4);

    const float2* W2 = reinterpret_cast<const float2*>(W_ops);
    const float2* C2 = reinterpret_cast<const float2*>(W_cat);

    if (blk >= EBLK + SBLK) {                        // linear weights for i
        int i = blk - (EBLK + SBLK);
        float l0 = 0.f, l1 = 0.f;
        #pragma unroll
        for (int j = 0; j < NC; j++) {
            float2 Pij = W2[((i*NC+j)*4 + 0)*DD + d];
            float2 Pji = W2[((j*NC+i)*4 + 0)*DD + d];
            float2 Xij = W2[((i*NC+j)*4 + 2)*DD + d];
            float2 Xji = W2[((j*NC+i)*4 + 2)*DD + d];
            float2 Nij = W2[((i*NC+j)*4 + 3)*DD + d];
            float2 Nji = W2[((j*NC+i)*4 + 3)*DD + d];
            float2 Cp  = C2[(i*NC+j)*(2*DD) + d];        // p half, row d
            float2 Cq  = C2[(j*NC+i)*(2*DD) + DD + d];   // q half, row 64+d
            l0 += w0*(Pij.x+Pji.x) + 0.5f*w2*(Xij.x+Xji.x)
                + 0.5f*w3*(Nij.x+Nji.x) + w4*(Cp.x+Cq.x);
            l1 += w0*(Pij.y+Pji.y) + 0.5f*w2*(Xij.y+Xji.y)
                + 0.5f*w3*(Nij.y+Nji.y) + w4*(Cp.y+Cq.y);
        }
        reinterpret_cast<float4*>(g_w)[(d*NENT + i) * 2] = make_float4(l0, l0, l1, l1);
        return;
    }

    // packed pair / diag entry
    int entry = blk;
    if (entry < NC) {                                // diagonal e_i^2 weight
        int i = entry;
        float2 Mii = W2[((i*NC+i)*4 + 1)*DD + d];
        reinterpret_cast<float4*>(g_w)[(d*NENT + i) * 2 + 1] =
            make_float4(w1*Mii.x, w1*Mii.x, w1*Mii.y, w1*Mii.y);
        return;
    }
    int p = entry - NC;
    int i = 0, rem = p;
    while (rem >= NC - 1 - i) { rem -= NC - 1 - i; i++; }
    int j = i + 1 + rem;

    float2 Mij = W2[((i*NC+j)*4 + 1)*DD + d];
    float2 Mji = W2[((j*NC+i)*4 + 1)*DD + d];
    float2 Xij = W2[((i*NC+j)*4 + 2)*DD + d];
    float2 Xji = W2[((j*NC+i)*4 + 2)*DD + d];
    float2 Nij = W2[((i*NC+j)*4 + 3)*DD + d];
    float2 Nji = W2[((j*NC+i)*4 + 3)*DD + d];
    float wx = w1*(Mij.x+Mji.x);
    float wy = w1*(Mij.y+Mji.y);
    float wz = 0.5f*(w2*(Xij.x+Xji.x) - w3*(Nij.x+Nji.x));
    float ww = 0.5f*(w2*(Xij.y+Xji.y) - w3*(Nij.y+Nji.y));
    float4* dst = reinterpret_cast<float4*>(g_w) + (d*NENT + entry) * 2;
    dst[0] = make_float4(wx, wx, wy, wy);
    dst[1] = make_float4(wz, wz, ww, ww);
}

// ---------------- main kernel: pairwise compute -----------------------------------
// grid: (8, 64), 128 threads; 2 b per thread packed f32x2 (8*128*2 = 2048).
__global__ void __launch_bounds__(128)
main_kernel(const int* __restrict__ idx, const float* __restrict__ emb_mean,
            const float* __restrict__ v) {
    const int d  = blockIdx.y;
    const int b0 = blockIdx.x * 256;
    const int tid = threadIdx.x;

    __shared__ float swt[NENT * 8];
    __shared__ float mean_s[TBL];
    __shared__ float sp_s[TBL];

    {
        const float4* wp = reinterpret_cast<const float4*>(g_w) + d * NENT * 2;
        float4* s4 = reinterpret_cast<float4*>(swt);
        #pragma unroll
        for (int t = tid; t < NENT * 2; t += 128) s4[t] = wp[t];
        #pragma unroll
        for (int t = tid; t < TBL; t += 128) {
            mean_s[t] = emb_mean[t * DD + d];
            sp_s[t]   = g_sp[t * DD + d];
        }
    }
    __syncthreads();

    const int b  = b0 + tid;
    const int b2 = b + 128;
    const float vlo = v[b  * DD + d];
    const float vhi = v[b2 * DD + d];

    ull e2[NC];
    #pragma unroll
    for (int i = 0; i < NC; i++) {
        int iv  = idx[i * BB + b];
        int iv2 = idx[i * BB + b2];
        float elo = fmaf(sp_s[i * NE + iv],  vlo, mean_s[i * NE + iv]);
        float ehi = fmaf(sp_s[i * NE + iv2], vhi, mean_s[i * NE + iv2]);
        e2[i] = pack2(elo, ehi);
    }

    ull A0 = 0ULL, A1 = 0ULL;
    const ulonglong2* sw2 = reinterpret_cast<const ulonglong2*>(swt);

    #pragma unroll
    for (int i = 0; i < NC; i++) {
        ulonglong2 wl = sw2[i * 2 + 0];
        ulonglong2 wd = sw2[i * 2 + 1];
        ull p2 = mul2(e2[i], e2[i]);
        A0 = fma2(e2[i], wl.x, A0);
        A1 = fma2(e2[i], wl.y, A1);
        A0 = fma2(p2,    wd.x, A0);
        A1 = fma2(p2,    wd.y, A1);
    }

    const ull NEG1 = 0xBF800000BF800000ULL;
    int pi = NC;
    #pragma unroll
    for (int i = 0; i < NC - 1; i++) {
        #pragma unroll
        for (int j = i + 1; j < NC; j++) {
            ulonglong2 wm = sw2[pi * 2 + 0];
            ulonglong2 wa = sw2[pi * 2 + 1];
            pi++;
            ull p2 = mul2(e2[i], e2[j]);
            ull df = fma2(e2[j], NEG1, e2[i]);
            ull ad = df & 0x7FFFFFFF7FFFFFFFULL;
            A0 = fma2(p2, wm.x, A0);
            A1 = fma2(p2, wm.y, A1);
            A0 = fma2(ad, wa.x, A0);
            A1 = fma2(ad, wa.y, A1);
        }
    }

    float a0l, a0h, a1l, a1h;
    unpack2(A0, a0l, a0h);
    unpack2(A1, a1l, a1h);
    g_partial[(b  * 2 + 0) * DD + d] = a0l;
    g_partial[(b  * 2 + 1) * DD + d] = a1l;
    g_partial[(b2 * 2 + 0) * DD + d] = a0h;
    g_partial[(b2 * 2 + 1) * DD + d] = a1h;
}

// ---------------- reduce: one warp per output over d ------------------------------
__global__ void __launch_bounds__(256)
reduce_kernel(float* __restrict__ out) {
    int warp = (blockIdx.x * 256 + threadIdx.x) >> 5;   // 0..4095
    int lane = threadIdx.x & 31;
    const float* p = g_partial + warp * DD;
    float s = p[lane] + p[lane + 32];
    #pragma unroll
    for (int o = 16; o > 0; o >>= 1)
        s += __shfl_down_sync(0xFFFFFFFFu, s, o);
    if (lane == 0) out[warp] = s;
}

// ---------------- launch ----------------------------------------------------------
extern "C" void kernel_launch(void* const* d_in, const int* in_sizes, int n_in,
                              void* d_out, int out_size) {
    const int*   idx       = (const int*)  d_in[0];
    const float* emb_mean  = (const float*)d_in[1];
    const float* emb_std   = (const float*)d_in[2];
    const float* v         = (const float*)d_in[3];
    const float* W_ops     = (const float*)d_in[4];
    const float* W_cat     = (const float*)d_in[5];
    const float* log_alpha = (const float*)d_in[6];
    float* out = (float*)d_out;

    prep_kernel<<<PBLK, 64>>>(W_ops, W_cat, log_alpha, emb_std);
    main_kernel<<<dim3(8, DD), 128>>>(idx, emb_mean, v);
    reduce_kernel<<<(BB * 2) / 8, 256>>>(out);
}

// round 9
// speedup vs baseline: 1.3985x; 1.1701x over previous
#include <cuda_runtime.h>
#include <math.h>

// Problem constants
#define NC    22            // columns
#define NE    12            // embeddings per column
#define DD    64            // feature dim
#define BB    2048          // batch
#define NPAIR 231           // 22 choose 2
#define NENT  253           // 22 lin/diag entries + 231 pair entries
#define TBL   (NC*NE)       // 264 table rows

typedef unsigned long long ull;

// ---------------- device scratch ----------------
__device__ float g_sp[TBL * DD];            // 0.01*softplus(emb_std), flat [t*DD+d]
__device__ float g_w[DD * NENT * 8];        // per-d lane-duplicated packed weights
__device__ float g_partial[BB * 2 * DD];    // partial[(b*2+k)][d]

// ---------------- f32x2 packed helpers (sm_100a+) ----------------
__device__ __forceinline__ ull pack2(float lo, float hi) {
    ull r; asm("mov.b64 %0, {%1, %2};" : "=l"(r) : "f"(lo), "f"(hi)); return r;
}
__device__ __forceinline__ void unpack2(ull x, float& lo, float& hi) {
    asm("mov.b64 {%0, %1}, %2;" : "=f"(lo), "=f"(hi) : "l"(x));
}
__device__ __forceinline__ ull fma2(ull a, ull b, ull c) {
    ull r; asm("fma.rn.f32x2 %0, %1, %2, %3;" : "=l"(r) : "l"(a), "l"(b), "l"(c)); return r;
}
__device__ __forceinline__ ull mul2(ull a, ull b) {
    ull r; asm("mul.rn.f32x2 %0, %1, %2;" : "=l"(r) : "l"(a), "l"(b)); return r;
}

__device__ __forceinline__ void softmax5(const float* __restrict__ log_alpha,
                                         float& w0, float& w1, float& w2,
                                         float& w3, float& w4) {
    float la[5], w[5];
    float mx = -1e30f, s = 0.f;
    #pragma unroll
    for (int z = 0; z < 5; z++) { la[z] = __ldg(log_alpha + z); mx = fmaxf(mx, la[z]); }
    #pragma unroll
    for (int z = 0; z < 5; z++) { w[z] = expf(la[z] - mx); s += w[z]; }
    float inv = 1.0f / s;
    w0 = w[0]*inv; w1 = w[1]*inv; w2 = w[2]*inv; w3 = w[3]*inv; w4 = w[4]*inv;
}

// ---------------- prep kernel: every thread MLP-rich, no serial memory loops -----
// block layout (256 threads each):
//   [0, 22):   linear weights; block=i, thread=(d, jchunk 0..3), each sums 5-6 j's
//   [22, 28):  diagonal weights; one (i,d) item per thread (1408 items)
//   [28, 86):  pair weights; one (pair,d) item per thread (14784 items)
//   [86, 152): softplus table; one element per thread (16896 items)
#define LIN_B0   0
#define DIAG_B0  22
#define PAIR_B0  28
#define SP_B0    86
#define PBLK     152

__global__ void __launch_bounds__(256)
prep_kernel(const float* __restrict__ W_ops, const float* __restrict__ W_cat,
            const float* __restrict__ log_alpha, const float* __restrict__ emb_std) {
    const int blk = blockIdx.x;
    const int tid = threadIdx.x;

    // ---- softplus table ----
    if (blk >= SP_B0) {
        int u = (blk - SP_B0) * 256 + tid;      // < TBL*DD = 16896 exactly
        float x = emb_std[u];
        g_sp[u] = 0.01f * (fmaxf(x, 0.0f) + log1pf(expf(-fabsf(x))));
        return;
    }

    float w0, w1, w2, w3, w4;
    softmax5(log_alpha, w0, w1, w2, w3, w4);
    const float2* W2 = reinterpret_cast<const float2*>(W_ops);
    const float2* C2 = reinterpret_cast<const float2*>(W_cat);

    if (blk >= PAIR_B0) {
        // ---- pair weights: one (p, d) per thread ----
        int t = (blk - PAIR_B0) * 256 + tid;
        if (t >= NPAIR * DD) return;
        int d = t & 63;
        int p = t >> 6;
        int i = 0, rem = p;
        while (rem >= NC - 1 - i) { rem -= NC - 1 - i; i++; }
        int j = i + 1 + rem;

        float2 Mij = W2[((i*NC+j)*4 + 1)*DD + d];
        float2 Mji = W2[((j*NC+i)*4 + 1)*DD + d];
        float2 Xij = W2[((i*NC+j)*4 + 2)*DD + d];
        float2 Xji = W2[((j*NC+i)*4 + 2)*DD + d];
        float2 Nij = W2[((i*NC+j)*4 + 3)*DD + d];
        float2 Nji = W2[((j*NC+i)*4 + 3)*DD + d];
        float wx = w1*(Mij.x+Mji.x);
        float wy = w1*(Mij.y+Mji.y);
        float wz = 0.5f*(w2*(Xij.x+Xji.x) - w3*(Nij.x+Nji.x));
        float ww = 0.5f*(w2*(Xij.y+Xji.y) - w3*(Nij.y+Nji.y));
        float4* dst = reinterpret_cast<float4*>(g_w) + (d*NENT + NC + p) * 2;
        dst[0] = make_float4(wx, wx, wy, wy);
        dst[1] = make_float4(wz, wz, ww, ww);
        return;
    }

    if (blk >= DIAG_B0) {
        // ---- diagonal weights: one (i, d) per thread ----
        int t = (blk - DIAG_B0) * 256 + tid;
        if (t >= NC * DD) return;
        int d = t & 63;
        int i = t >> 6;
        float2 Mii = W2[((i*NC+i)*4 + 1)*DD + d];
        reinterpret_cast<float4*>(g_w)[(d*NENT + i) * 2 + 1] =
            make_float4(w1*Mii.x, w1*Mii.x, w1*Mii.y, w1*Mii.y);
        return;
    }

    // ---- linear weights: block = i; thread = (d, jchunk); 4-way smem reduce ----
    __shared__ float2 lsum[4][DD];
    {
        int i = blk;
        int d = tid & 63;
        int c = tid >> 6;            // 0..3
        float l0 = 0.f, l1 = 0.f;
        #pragma unroll
        for (int j = c; j < NC; j += 4) {
            float2 Pij = W2[((i*NC+j)*4 + 0)*DD + d];
            float2 Pji = W2[((j*NC+i)*4 + 0)*DD + d];
            float2 Xij = W2[((i*NC+j)*4 + 2)*DD + d];
            float2 Xji = W2[((j*NC+i)*4 + 2)*DD + d];
            float2 Nij = W2[((i*NC+j)*4 + 3)*DD + d];
            float2 Nji = W2[((j*NC+i)*4 + 3)*DD + d];
            float2 Cp  = C2[(i*NC+j)*(2*DD) + d];        // p half, row d
            float2 Cq  = C2[(j*NC+i)*(2*DD) + DD + d];   // q half, row 64+d
            l0 += w0*(Pij.x+Pji.x) + 0.5f*w2*(Xij.x+Xji.x)
                + 0.5f*w3*(Nij.x+Nji.x) + w4*(Cp.x+Cq.x);
            l1 += w0*(Pij.y+Pji.y) + 0.5f*w2*(Xij.y+Xji.y)
                + 0.5f*w3*(Nij.y+Nji.y) + w4*(Cp.y+Cq.y);
        }
        lsum[c][d] = make_float2(l0, l1);
        __syncthreads();
        if (c == 0) {
            float2 a = lsum[0][d], b2_ = lsum[1][d], cc = lsum[2][d], dd_ = lsum[3][d];
            float L0 = (a.x + b2_.x) + (cc.x + dd_.x);
            float L1 = (a.y + b2_.y) + (cc.y + dd_.y);
            reinterpret_cast<float4*>(g_w)[(d*NENT + i) * 2] =
                make_float4(L0, L0, L1, L1);
        }
    }
}

// ---------------- main kernel: pairwise compute -----------------------------------
// grid: (8, 64), 128 threads; 2 b per thread packed f32x2 (8*128*2 = 2048).
__global__ void __launch_bounds__(128)
main_kernel(const int* __restrict__ idx, const float* __restrict__ emb_mean,
            const float* __restrict__ v) {
    const int d  = blockIdx.y;
    const int b0 = blockIdx.x * 256;
    const int tid = threadIdx.x;

    __shared__ float swt[NENT * 8];
    __shared__ float mean_s[TBL];
    __shared__ float sp_s[TBL];

    {
        const float4* wp = reinterpret_cast<const float4*>(g_w) + d * NENT * 2;
        float4* s4 = reinterpret_cast<float4*>(swt);
        #pragma unroll
        for (int t = tid; t < NENT * 2; t += 128) s4[t] = wp[t];
        #pragma unroll
        for (int t = tid; t < TBL; t += 128) {
            mean_s[t] = emb_mean[t * DD + d];
            sp_s[t]   = g_sp[t * DD + d];
        }
    }
    __syncthreads();

    const int b  = b0 + tid;
    const int b2 = b + 128;
    const float vlo = v[b  * DD + d];
    const float vhi = v[b2 * DD + d];

    ull e2[NC];
    #pragma unroll
    for (int i = 0; i < NC; i++) {
        int iv  = idx[i * BB + b];
        int iv2 = idx[i * BB + b2];
        float elo = fmaf(sp_s[i * NE + iv],  vlo, mean_s[i * NE + iv]);
        float ehi = fmaf(sp_s[i * NE + iv2], vhi, mean_s[i * NE + iv2]);
        e2[i] = pack2(elo, ehi);
    }

    ull A0 = 0ULL, A1 = 0ULL;
    const ulonglong2* sw2 = reinterpret_cast<const ulonglong2*>(swt);

    #pragma unroll
    for (int i = 0; i < NC; i++) {
        ulonglong2 wl = sw2[i * 2 + 0];
        ulonglong2 wd = sw2[i * 2 + 1];
        ull p2 = mul2(e2[i], e2[i]);
        A0 = fma2(e2[i], wl.x, A0);
        A1 = fma2(e2[i], wl.y, A1);
        A0 = fma2(p2,    wd.x, A0);
        A1 = fma2(p2,    wd.y, A1);
    }

    const ull NEG1 = 0xBF800000BF800000ULL;
    int pi = NC;
    #pragma unroll
    for (int i = 0; i < NC - 1; i++) {
        #pragma unroll
        for (int j = i + 1; j < NC; j++) {
            ulonglong2 wm = sw2[pi * 2 + 0];
            ulonglong2 wa = sw2[pi * 2 + 1];
            pi++;
            ull p2 = mul2(e2[i], e2[j]);
            ull df = fma2(e2[j], NEG1, e2[i]);
            ull ad = df & 0x7FFFFFFF7FFFFFFFULL;
            A0 = fma2(p2, wm.x, A0);
            A1 = fma2(p2, wm.y, A1);
            A0 = fma2(ad, wa.x, A0);
            A1 = fma2(ad, wa.y, A1);
        }
    }

    float a0l, a0h, a1l, a1h;
    unpack2(A0, a0l, a0h);
    unpack2(A1, a1l, a1h);
    g_partial[(b  * 2 + 0) * DD + d] = a0l;
    g_partial[(b  * 2 + 1) * DD + d] = a1l;
    g_partial[(b2 * 2 + 0) * DD + d] = a0h;
    g_partial[(b2 * 2 + 1) * DD + d] = a1h;
}

// ---------------- reduce: one warp per output over d ------------------------------
__global__ void __launch_bounds__(256)
reduce_kernel(float* __restrict__ out) {
    int warp = (blockIdx.x * 256 + threadIdx.x) >> 5;   // 0..4095
    int lane = threadIdx.x & 31;
    const float* p = g_partial + warp * DD;
    float s = p[lane] + p[lane + 32];
    #pragma unroll
    for (int o = 16; o > 0; o >>= 1)
        s += __shfl_down_sync(0xFFFFFFFFu, s, o);
    if (lane == 0) out[warp] = s;
}

// ---------------- launch ----------------------------------------------------------
extern "C" void kernel_launch(void* const* d_in, const int* in_sizes, int n_in,
                              void* d_out, int out_size) {
    const int*   idx       = (const int*)  d_in[0];
    const float* emb_mean  = (const float*)d_in[1];
    const float* emb_std   = (const float*)d_in[2];
    const float* v         = (const float*)d_in[3];
    const float* W_ops     = (const float*)d_in[4];
    const float* W_cat     = (const float*)d_in[5];
    const float* log_alpha = (const float*)d_in[6];
    float* out = (float*)d_out;

    prep_kernel<<<PBLK, 256>>>(W_ops, W_cat, log_alpha, emb_std);
    main_kernel<<<dim3(8, DD), 128>>>(idx, emb_mean, v);
    reduce_kernel<<<(BB * 2) / 8, 256>>>(out);
}

// round 10
// speedup vs baseline: 1.4386x; 1.0287x over previous
#include <cuda_runtime.h>
#include <math.h>

// Problem constants
#define NC    22            // columns
#define NE    12            // embeddings per column
#define DD    64            // feature dim
#define BB    2048          // batch
#define NPAIR 231           // 22 choose 2
#define NENT  253           // 22 lin/diag entries + 231 pair entries
#define TBL   (NC*NE)       // 264 table rows

typedef unsigned long long ull;

// ---------------- device scratch ----------------
__device__ float g_sp[TBL * DD];            // 0.01*softplus(emb_std), flat [t*DD+d]
__device__ float g_w[DD * NENT * 8];        // per-d lane-duplicated packed weights
__device__ float g_partial[BB * 2 * DD];    // partial[(b*2+k)][d]

// ---------------- f32x2 packed helpers (sm_100a+) ----------------
__device__ __forceinline__ ull pack2(float lo, float hi) {
    ull r; asm("mov.b64 %0, {%1, %2};" : "=l"(r) : "f"(lo), "f"(hi)); return r;
}
__device__ __forceinline__ void unpack2(ull x, float& lo, float& hi) {
    asm("mov.b64 {%0, %1}, %2;" : "=f"(lo), "=f"(hi) : "l"(x));
}
__device__ __forceinline__ ull fma2(ull a, ull b, ull c) {
    ull r; asm("fma.rn.f32x2 %0, %1, %2, %3;" : "=l"(r) : "l"(a), "l"(b), "l"(c)); return r;
}
__device__ __forceinline__ ull mul2(ull a, ull b) {
    ull r; asm("mul.rn.f32x2 %0, %1, %2;" : "=l"(r) : "l"(a), "l"(b)); return r;
}

__device__ __forceinline__ void softmax5(const float* __restrict__ log_alpha,
                                         float& w0, float& w1, float& w2,
                                         float& w3, float& w4) {
    float la[5], w[5];
    float mx = -1e30f, s = 0.f;
    #pragma unroll
    for (int z = 0; z < 5; z++) { la[z] = __ldg(log_alpha + z); mx = fmaxf(mx, la[z]); }
    #pragma unroll
    for (int z = 0; z < 5; z++) { w[z] = expf(la[z] - mx); s += w[z]; }
    float inv = 1.0f / s;
    w0 = w[0]*inv; w1 = w[1]*inv; w2 = w[2]*inv; w3 = w[3]*inv; w4 = w[4]*inv;
}

// ---------------- prep kernel: 128-thr blocks, one small-MLP item per thread -----
// block layout:
//   [0, 88):    linear weights; block covers 16 (i,d) items x 8 streams
//   [88, 99):   diagonal weights; one (i,d) per thread (1408 items)
//   [99, 215):  pair weights; one (pair,d) per thread (14784 items)
//   [215, 347): softplus table; one element per thread (16896 items)
#define LIN_B0   0
#define DIAG_B0  88
#define PAIR_B0  99
#define SP_B0    215
#define PBLK     347

__global__ void __launch_bounds__(128)
prep_kernel(const float* __restrict__ W_ops, const float* __restrict__ W_cat,
            const float* __restrict__ log_alpha, const float* __restrict__ emb_std) {
    const int blk = blockIdx.x;
    const int tid = threadIdx.x;

    // ---- softplus table ----
    if (blk >= SP_B0) {
        int u = (blk - SP_B0) * 128 + tid;      // < TBL*DD = 16896 exactly
        float x = emb_std[u];
        g_sp[u] = 0.01f * (fmaxf(x, 0.0f) + log1pf(expf(-fabsf(x))));
        return;
    }

    float w0, w1, w2, w3, w4;
    softmax5(log_alpha, w0, w1, w2, w3, w4);
    const float2* W2 = reinterpret_cast<const float2*>(W_ops);
    const float2* C2 = reinterpret_cast<const float2*>(W_cat);

    if (blk >= PAIR_B0) {
        // ---- pair weights: one (p, d) per thread ----
        int t = (blk - PAIR_B0) * 128 + tid;
        if (t >= NPAIR * DD) return;
        int d = t & 63;
        int p = t >> 6;
        int i = 0, rem = p;
        while (rem >= NC - 1 - i) { rem -= NC - 1 - i; i++; }
        int j = i + 1 + rem;

        float2 Mij = W2[((i*NC+j)*4 + 1)*DD + d];
        float2 Mji = W2[((j*NC+i)*4 + 1)*DD + d];
        float2 Xij = W2[((i*NC+j)*4 + 2)*DD + d];
        float2 Xji = W2[((j*NC+i)*4 + 2)*DD + d];
        float2 Nij = W2[((i*NC+j)*4 + 3)*DD + d];
        float2 Nji = W2[((j*NC+i)*4 + 3)*DD + d];
        float wx = w1*(Mij.x+Mji.x);
        float wy = w1*(Mij.y+Mji.y);
        float wz = 0.5f*(w2*(Xij.x+Xji.x) - w3*(Nij.x+Nji.x));
        float ww = 0.5f*(w2*(Xij.y+Xji.y) - w3*(Nij.y+Nji.y));
        float4* dst = reinterpret_cast<float4*>(g_w) + (d*NENT + NC + p) * 2;
        dst[0] = make_float4(wx, wx, wy, wy);
        dst[1] = make_float4(wz, wz, ww, ww);
        return;
    }

    if (blk >= DIAG_B0) {
        // ---- diagonal weights: one (i, d) per thread ----
        int t = (blk - DIAG_B0) * 128 + tid;    // < NC*DD = 1408 exactly
        int d = t & 63;
        int i = t >> 6;
        float2 Mii = W2[((i*NC+i)*4 + 1)*DD + d];
        reinterpret_cast<float4*>(g_w)[(d*NENT + i) * 2 + 1] =
            make_float4(w1*Mii.x, w1*Mii.x, w1*Mii.y, w1*Mii.y);
        return;
    }

    // ---- linear weights: 8-way stream split ----
    // thread = (il 0..15 -> (i,d) item, c 0..7 -> stream); 22 uniform-stride loads
    __shared__ float2 ls[8][16];
    {
        const int il = tid & 15;
        const int c  = tid >> 4;                 // stream id
        const int item = blk * 16 + il;          // < 1408 (88*16 exactly)
        const int i = item >> 6;
        const int d = item & 63;

        const float2* base;
        int stride;
        if (c < 6) {
            int o = (c >> 1) == 0 ? 0 : ((c >> 1) == 1 ? 2 : 3);   // op: P,X,N
            if ((c & 1) == 0) { base = W2 + (i*NC*4 + o)*DD + d; stride = 4*DD; }
            else              { base = W2 + (i*4 + o)*DD + d;     stride = NC*4*DD; }
        } else if (c == 6)    { base = C2 + i*NC*2*DD + d;        stride = 2*DD; }
        else                  { base = C2 + i*2*DD + DD + d;      stride = NC*2*DD; }

        float a0 = 0.f, a1 = 0.f;
        #pragma unroll
        for (int j = 0; j < NC; j++) {
            float2 q = base[j * stride];
            a0 += q.x; a1 += q.y;
        }
        float wc = (c < 2) ? w0 : (c < 4 ? 0.5f*w2 : (c < 6 ? 0.5f*w3 : w4));
        ls[c][il] = make_float2(a0 * wc, a1 * wc);
        __syncthreads();
        if (c == 0) {
            float L0 = 0.f, L1 = 0.f;
            #pragma unroll
            for (int s = 0; s < 8; s++) { L0 += ls[s][il].x; L1 += ls[s][il].y; }
            reinterpret_cast<float4*>(g_w)[(d*NENT + i) * 2] =
                make_float4(L0, L0, L1, L1);
        }
    }
}

// ---------------- main kernel: pairwise compute -----------------------------------
// grid: (8, 64), 128 threads; 2 b per thread packed f32x2 (8*128*2 = 2048).
__global__ void __launch_bounds__(128)
main_kernel(const int* __restrict__ idx, const float* __restrict__ emb_mean,
            const float* __restrict__ v) {
    const int d  = blockIdx.y;
    const int b0 = blockIdx.x * 256;
    const int tid = threadIdx.x;

    __shared__ float swt[NENT * 8];
    __shared__ float mean_s[TBL];
    __shared__ float sp_s[TBL];

    {
        const float4* wp = reinterpret_cast<const float4*>(g_w) + d * NENT * 2;
        float4* s4 = reinterpret_cast<float4*>(swt);
        #pragma unroll
        for (int t = tid; t < NENT * 2; t += 128) s4[t] = wp[t];
        #pragma unroll
        for (int t = tid; t < TBL; t += 128) {
            mean_s[t] = emb_mean[t * DD + d];
            sp_s[t]   = g_sp[t * DD + d];
        }
    }
    __syncthreads();

    const int b  = b0 + tid;
    const int b2 = b + 128;
    const float vlo = v[b  * DD + d];
    const float vhi = v[b2 * DD + d];

    ull e2[NC];
    #pragma unroll
    for (int i = 0; i < NC; i++) {
        int iv  = idx[i * BB + b];
        int iv2 = idx[i * BB + b2];
        float elo = fmaf(sp_s[i * NE + iv],  vlo, mean_s[i * NE + iv]);
        float ehi = fmaf(sp_s[i * NE + iv2], vhi, mean_s[i * NE + iv2]);
        e2[i] = pack2(elo, ehi);
    }

    ull A0 = 0ULL, A1 = 0ULL;
    const ulonglong2* sw2 = reinterpret_cast<const ulonglong2*>(swt);

    #pragma unroll
    for (int i = 0; i < NC; i++) {
        ulonglong2 wl = sw2[i * 2 + 0];
        ulonglong2 wd = sw2[i * 2 + 1];
        ull p2 = mul2(e2[i], e2[i]);
        A0 = fma2(e2[i], wl.x, A0);
        A1 = fma2(e2[i], wl.y, A1);
        A0 = fma2(p2,    wd.x, A0);
        A1 = fma2(p2,    wd.y, A1);
    }

    const ull NEG1 = 0xBF800000BF800000ULL;
    int pi = NC;
    #pragma unroll
    for (int i = 0; i < NC - 1; i++) {
        #pragma unroll
        for (int j = i + 1; j < NC; j++) {
            ulonglong2 wm = sw2[pi * 2 + 0];
            ulonglong2 wa = sw2[pi * 2 + 1];
            pi++;
            ull p2 = mul2(e2[i], e2[j]);
            ull df = fma2(e2[j], NEG1, e2[i]);
            ull ad = df & 0x7FFFFFFF7FFFFFFFULL;
            A0 = fma2(p2, wm.x, A0);
            A1 = fma2(p2, wm.y, A1);
            A0 = fma2(ad, wa.x, A0);
            A1 = fma2(ad, wa.y, A1);
        }
    }

    float a0l, a0h, a1l, a1h;
    unpack2(A0, a0l, a0h);
    unpack2(A1, a1l, a1h);
    g_partial[(b  * 2 + 0) * DD + d] = a0l;
    g_partial[(b  * 2 + 1) * DD + d] = a1l;
    g_partial[(b2 * 2 + 0) * DD + d] = a0h;
    g_partial[(b2 * 2 + 1) * DD + d] = a1h;
}

// ---------------- reduce: one warp per output over d ------------------------------
__global__ void __launch_bounds__(256)
reduce_kernel(float* __restrict__ out) {
    int warp = (blockIdx.x * 256 + threadIdx.x) >> 5;   // 0..4095
    int lane = threadIdx.x & 31;
    const float* p = g_partial + warp * DD;
    float s = p[lane] + p[lane + 32];
    #pragma unroll
    for (int o = 16; o > 0; o >>= 1)
        s += __shfl_down_sync(0xFFFFFFFFu, s, o);
    if (lane == 0) out[warp] = s;
}

// ---------------- launch ----------------------------------------------------------
extern "C" void kernel_launch(void* const* d_in, const int* in_sizes, int n_in,
                              void* d_out, int out_size) {
    const int*   idx       = (const int*)  d_in[0];
    const float* emb_mean  = (const float*)d_in[1];
    const float* emb_std   = (const float*)d_in[2];
    const float* v         = (const float*)d_in[3];
    const float* W_ops     = (const float*)d_in[4];
    const float* W_cat     = (const float*)d_in[5];
    const float* log_alpha = (const float*)d_in[6];
    float* out = (float*)d_out;

    prep_kernel<<<PBLK, 128>>>(W_ops, W_cat, log_alpha, emb_std);
    main_kernel<<<dim3(8, DD), 128>>>(idx, emb_mean, v);
    reduce_kernel<<<(BB * 2) / 8, 256>>>(out);
}